// round 14
// baseline (speedup 1.0000x reference)
#include <cuda_runtime.h>
#include <cuda_bf16.h>
#include <math.h>
#include <float.h>
#include <limits.h>
#include <stdint.h>

// Problem constants
#define Bb 2
#define Tt 2048
#define Dd 1024
#define Nn 16
#define Kk 8
#define Hh 128
#define Gg 2
#define Mrows (Bb*Tt)          // 4096

static constexpr float EPSf   = 1e-6f;
static constexpr float LOG_THETA = 13.815510557964274f;  // ln(1e6)
static constexpr float SCALEf = 0.08838834764831845f;    // 128^-0.5

// ---------------------------------------------------------------------------
// Scratch (allocation-free rule: __device__ globals)
// ---------------------------------------------------------------------------
__device__ int    g_pos[Mrows];
__device__ float2 g_rope[(size_t)Mrows * 64];            // (sin, cos) per (row, i)
__device__ float  g_qkv[(size_t)Mrows * 4096];           // fp32 q|k cols 0..3071

// bf16 split buffers
__device__ __nv_bfloat16 g_xhi[(size_t)Mrows * Dd];
__device__ __nv_bfloat16 g_xlo[(size_t)Mrows * Dd];
__device__ __nv_bfloat16 g_atthi[(size_t)Mrows * Nn * Hh];   // attn out [row][n*H]
__device__ __nv_bfloat16 g_attlo[(size_t)Mrows * Nn * Hh];
__device__ __nv_bfloat16 g_wqkvT_hi[(size_t)4096 * Dd];      // [wq|wk|wv]^T rows
__device__ __nv_bfloat16 g_wqkvT_lo[(size_t)4096 * Dd];
__device__ __nv_bfloat16 g_woT_hi[(size_t)Dd * (Nn*Hh)];
__device__ __nv_bfloat16 g_woT_lo[(size_t)Dd * (Nn*Hh)];

// head-major bf16 split q/k/v for attention: [b][head][t][h]
__device__ __nv_bfloat16 g_qhh[(size_t)Bb * Nn * Tt * Hh];
__device__ __nv_bfloat16 g_qhl[(size_t)Bb * Nn * Tt * Hh];
__device__ __nv_bfloat16 g_khh[(size_t)Bb * Kk * Tt * Hh];
__device__ __nv_bfloat16 g_khl[(size_t)Bb * Kk * Tt * Hh];
__device__ __nv_bfloat16 g_vhh[(size_t)Bb * Kk * Tt * Hh];
__device__ __nv_bfloat16 g_vhl[(size_t)Bb * Kk * Tt * Hh];

// ---------------------------------------------------------------------------
// PTX helpers
// ---------------------------------------------------------------------------
__device__ __forceinline__ uint32_t smem_u32(const void* p) {
    uint32_t a;
    asm("{ .reg .u64 t; cvta.to.shared.u64 t, %1; cvt.u32.u64 %0, t; }"
        : "=r"(a) : "l"(p));
    return a;
}
#define SW128(off) ((off) ^ (((off) >> 3) & 0x70))

#define CP_ASYNC16(saddr, gaddr) \
    asm volatile("cp.async.cg.shared.global [%0], [%1], 16;" \
        :: "r"(saddr), "l"(gaddr) : "memory")
#define CP_COMMIT() asm volatile("cp.async.commit_group;" ::: "memory")
#define CP_WAIT(n)  asm volatile("cp.async.wait_group %0;" :: "n"(n) : "memory")

#define LDSM_X4(r, addr) \
    asm volatile("ldmatrix.sync.aligned.m8n8.x4.shared.b16 {%0,%1,%2,%3}, [%4];" \
        : "=r"((r)[0]), "=r"((r)[1]), "=r"((r)[2]), "=r"((r)[3]) : "r"(addr))
#define LDSM_X4_T(r, addr) \
    asm volatile("ldmatrix.sync.aligned.m8n8.x4.trans.shared.b16 {%0,%1,%2,%3}, [%4];" \
        : "=r"((r)[0]), "=r"((r)[1]), "=r"((r)[2]), "=r"((r)[3]) : "r"(addr))

#define MMA16816(d, a, b0r, b1r) \
    asm volatile("mma.sync.aligned.m16n8k16.row.col.f32.bf16.bf16.f32 " \
        "{%0,%1,%2,%3}, {%4,%5,%6,%7}, {%8,%9}, {%0,%1,%2,%3};" \
        : "+f"((d)[0]), "+f"((d)[1]), "+f"((d)[2]), "+f"((d)[3]) \
        : "r"((a)[0]), "r"((a)[1]), "r"((a)[2]), "r"((a)[3]), \
          "r"((b0r)), "r"((b1r)))

__device__ __forceinline__ uint32_t split2(float x0, float x1, uint32_t& lopack) {
    __nv_bfloat16 h0 = __float2bfloat16(x0), h1 = __float2bfloat16(x1);
    float r0 = x0 - __bfloat162float(h0), r1 = x1 - __bfloat162float(h1);
    __nv_bfloat16 g0 = __float2bfloat16(r0), g1 = __float2bfloat16(r1);
    lopack = (uint32_t)__bfloat16_as_ushort(g0) | ((uint32_t)__bfloat16_as_ushort(g1) << 16);
    return (uint32_t)__bfloat16_as_ushort(h0) | ((uint32_t)__bfloat16_as_ushort(h1) << 16);
}

// ---------------------------------------------------------------------------
// positions_from_segment_ids
// ---------------------------------------------------------------------------
__global__ void pos_kernel(const int* __restrict__ seg) {
    int b = blockIdx.x;
    int tid = threadIdx.x;
    __shared__ int sv[256], si[256];
    int bv = INT_MIN, bi = INT_MAX;
    for (int t = tid; t < Tt; t += 256) {
        int v = seg[b * Tt + t];
        if (v > bv) { bv = v; bi = t; }
    }
    sv[tid] = bv; si[tid] = bi;
    __syncthreads();
    for (int o = 128; o; o >>= 1) {
        if (tid < o) {
            if (sv[tid + o] > sv[tid] ||
                (sv[tid + o] == sv[tid] && si[tid + o] < si[tid])) {
                sv[tid] = sv[tid + o]; si[tid] = si[tid + o];
            }
        }
        __syncthreads();
    }
    int off = si[0];
    for (int t = tid; t < Tt; t += 256) {
        int v = seg[b * Tt + t];
        g_pos[b * Tt + t] = (v != 0) ? (t - off) : (1 << 30);
    }
}

// ---------------------------------------------------------------------------
// RoPE sin/cos table
// ---------------------------------------------------------------------------
__global__ __launch_bounds__(256)
void rope_kernel() {
    int idx = blockIdx.x * 256 + threadIdx.x;
    int gr = idx >> 6, i = idx & 63;
    int pos = g_pos[gr];
    float inv_freq = __expf(-(float)i * (LOG_THETA / 64.0f));
    float ang = (float)pos * inv_freq;
    g_rope[idx] = make_float2(sinf(ang), cosf(ang));
}

// ---------------------------------------------------------------------------
// Unified conversion kernel. Block ranges (total 7168):
//   [0, 1024)      : x elementwise split (1M float4; 1024 blk x 256 thr x 4)
//   [1024, 3072)   : wq tsplit  src[1024,2048] -> dst rows 0..2047, ld 1024
//   [3072, 4096)   : wk tsplit  src[1024,1024] -> dst rows 2048..3071
//   [4096, 5120)   : wv tsplit  src[1024,1024] -> dst rows 3072..4095
//   [5120, 7168)   : wo tsplit  src[2048,1024] -> woT [1024,2048], ld 2048
// ---------------------------------------------------------------------------
__global__ __launch_bounds__(256)
void conv_all(const float* __restrict__ x,
              const float* __restrict__ wq, const float* __restrict__ wk,
              const float* __restrict__ wv, const float* __restrict__ wo) {
    int blk = blockIdx.x;
    if (blk < 1024) {
        size_t i = (size_t)blk * 1024 + threadIdx.x;
#pragma unroll
        for (int it = 0; it < 4; it++, i += 256) {
            float4 v = ((const float4*)x)[i];
            uint32_t l01, l23;
            uint32_t h01 = split2(v.x, v.y, l01);
            uint32_t h23 = split2(v.z, v.w, l23);
            ((uint2*)g_xhi)[i] = make_uint2(h01, h23);
            ((uint2*)g_xlo)[i] = make_uint2(l01, l23);
        }
        return;
    }
    // transpose-split: src [Kd, Nc] -> dst [Nc rows (+row_off), Kd cols (dstld)]
    const float* w; __nv_bfloat16 *hi, *lo;
    int Nc, nblk_x, row_off, dstld;
    if (blk < 3072)      { blk -= 1024; w = wq; Nc = 2048; nblk_x = 64; row_off = 0;
                           dstld = 1024; hi = g_wqkvT_hi; lo = g_wqkvT_lo; }
    else if (blk < 4096) { blk -= 3072; w = wk; Nc = 1024; nblk_x = 32; row_off = 2048;
                           dstld = 1024; hi = g_wqkvT_hi; lo = g_wqkvT_lo; }
    else if (blk < 5120) { blk -= 4096; w = wv; Nc = 1024; nblk_x = 32; row_off = 3072;
                           dstld = 1024; hi = g_wqkvT_hi; lo = g_wqkvT_lo; }
    else                 { blk -= 5120; w = wo; Nc = 1024; nblk_x = 32; row_off = 0;
                           dstld = 2048; hi = g_woT_hi; lo = g_woT_lo; }
    int bx = blk % nblk_x, by = blk / nblk_x;
    int n0 = bx * 32, k0 = by * 32;
    int tx = threadIdx.x & 31, ty = threadIdx.x >> 5;
    __shared__ float t[32][33];
    for (int i = ty; i < 32; i += 8)
        t[i][tx] = w[(size_t)(k0 + i) * Nc + n0 + tx];
    __syncthreads();
    for (int i = ty; i < 32; i += 8) {
        float v = t[tx][i];
        __nv_bfloat16 h = __float2bfloat16(v);
        __nv_bfloat16 l = __float2bfloat16(v - __bfloat162float(h));
        size_t o = (size_t)(row_off + n0 + i) * dstld + k0 + tx;
        hi[o] = h; lo[o] = l;
    }
}

// ---------------------------------------------------------------------------
// HMMA bf16-split GEMM, 256x128 CTA tile, 8 warps (4m x 2n of 64x64), BK=64.
// mode 0: fp32 store; mode 3: QKV combined (tiles>=24 -> V split store)
// ---------------------------------------------------------------------------
#define GSTAGE  98304
#define GA_LO   32768
#define GB_HI   65536
#define GB_LO   81920
#define GEMM_SMEM (2 * GSTAGE)

__global__ __launch_bounds__(256)
void gemm_hmma(const __nv_bfloat16* __restrict__ Ahi, const __nv_bfloat16* __restrict__ Alo,
               const __nv_bfloat16* __restrict__ Bhi, const __nv_bfloat16* __restrict__ Blo,
               float* __restrict__ C,
               __nv_bfloat16* __restrict__ Oh, __nv_bfloat16* __restrict__ Ol,
               int mode, int Nc, int Kd) {
    extern __shared__ char smc[];
    const int tid  = threadIdx.x;
    const int lane = tid & 31;
    const int wid  = tid >> 5;
    const int warp_m = wid & 3;
    const int warp_n = wid >> 2;
    const int m0 = blockIdx.y * 256, n0 = blockIdx.x * 128;

    const int u = tid & 7;
    const int r = tid >> 3;

    const uint32_t sbase = smem_u32(smc);
    const int nchunk = Kd >> 6;

    float d[4][8][4];
#pragma unroll
    for (int mt = 0; mt < 4; mt++)
#pragma unroll
        for (int nt = 0; nt < 8; nt++)
#pragma unroll
            for (int j = 0; j < 4; j++) d[mt][nt][j] = 0.f;

#define ISSUE_CHUNK(c, s) do {                                               \
    const int k0e = (c) * 64;                                                \
    uint32_t sa = sbase + (s) * GSTAGE;                                      \
    _Pragma("unroll")                                                        \
    for (int i = 0; i < 8; i++) {                                            \
        int row = r + i * 32;                                                \
        uint32_t so = SW128(row * 128 + u * 16);                             \
        CP_ASYNC16(sa + so,         Ahi + (size_t)(m0 + row) * Kd + k0e + u * 8); \
        CP_ASYNC16(sa + GA_LO + so, Alo + (size_t)(m0 + row) * Kd + k0e + u * 8); \
    }                                                                        \
    _Pragma("unroll")                                                        \
    for (int i = 0; i < 4; i++) {                                            \
        int row = r + i * 32;                                                \
        uint32_t so = SW128(row * 128 + u * 16);                             \
        CP_ASYNC16(sa + GB_HI + so, Bhi + (size_t)(n0 + row) * Kd + k0e + u * 8); \
        CP_ASYNC16(sa + GB_LO + so, Blo + (size_t)(n0 + row) * Kd + k0e + u * 8); \
    }                                                                        \
} while (0)

    ISSUE_CHUNK(0, 0);
    CP_COMMIT();

    for (int c = 0; c < nchunk; c++) {
        if (c + 1 < nchunk) { ISSUE_CHUNK(c + 1, (c + 1) & 1); CP_COMMIT(); CP_WAIT(1); }
        else                { CP_WAIT(0); }
        __syncthreads();

        const uint32_t sb = sbase + (c & 1) * GSTAGE;
#pragma unroll
        for (int s = 0; s < 4; s++) {
            uint32_t bH[8][2], bL[8][2];
#pragma unroll
            for (int np = 0; np < 4; np++) {
                int row  = warp_n * 64 + np * 16 + ((lane >> 4) & 1) * 8 + (lane & 7);
                int unit = s * 2 + ((lane >> 3) & 1);
                uint32_t addr = sb + GB_HI + SW128(row * 128 + unit * 16);
                uint32_t tmp[4];
                LDSM_X4(tmp, addr);
                bH[2*np][0] = tmp[0]; bH[2*np][1] = tmp[1];
                bH[2*np+1][0] = tmp[2]; bH[2*np+1][1] = tmp[3];
                LDSM_X4(tmp, addr + 16384);
                bL[2*np][0] = tmp[0]; bL[2*np][1] = tmp[1];
                bL[2*np+1][0] = tmp[2]; bL[2*np+1][1] = tmp[3];
            }
#pragma unroll
            for (int mt = 0; mt < 4; mt++) {
                uint32_t aH[4], aL[4];
                int row  = warp_m * 64 + mt * 16 + (lane & 7) + ((lane >> 3) & 1) * 8;
                int unit = s * 2 + (lane >> 4);
                uint32_t addr = sb + SW128(row * 128 + unit * 16);
                LDSM_X4(aH, addr);
                LDSM_X4(aL, addr + GA_LO);
#pragma unroll
                for (int nt = 0; nt < 8; nt++) {
                    MMA16816(d[mt][nt], aH, bH[nt][0], bH[nt][1]);
                    MMA16816(d[mt][nt], aH, bL[nt][0], bL[nt][1]);
                    MMA16816(d[mt][nt], aL, bH[nt][0], bH[nt][1]);
                }
            }
        }
        __syncthreads();
    }

    const bool vstore = (mode == 3) && (blockIdx.x >= 24);
    if (!vstore) {
#pragma unroll
        for (int mt = 0; mt < 4; mt++) {
#pragma unroll
            for (int nt = 0; nt < 8; nt++) {
                int row = m0 + warp_m * 64 + mt * 16 + (lane >> 2);
                int col = n0 + warp_n * 64 + nt * 8 + (lane & 3) * 2;
                *(float2*)&C[(size_t)row * Nc + col] =
                    make_float2(d[mt][nt][0], d[mt][nt][1]);
                *(float2*)&C[(size_t)(row + 8) * Nc + col] =
                    make_float2(d[mt][nt][2], d[mt][nt][3]);
            }
        }
    } else {
#pragma unroll
        for (int mt = 0; mt < 4; mt++) {
#pragma unroll
            for (int nt = 0; nt < 8; nt++) {
                int row = m0 + warp_m * 64 + mt * 16 + (lane >> 2);
                int col = n0 - 3072 + warp_n * 64 + nt * 8 + (lane & 3) * 2;
                int bq = row >> 11, t = row & 2047;
                int kv = col >> 7, h = col & 127;
                size_t o0 = ((size_t)(bq * Kk + kv) * Tt + t) * Hh + h;
                size_t o1 = ((size_t)(bq * Kk + kv) * Tt + t + 8) * Hh + h;
                uint32_t lop;
                uint32_t hip = split2(d[mt][nt][0], d[mt][nt][1], lop);
                *(uint32_t*)(Oh + o0) = hip;
                *(uint32_t*)(Ol + o0) = lop;
                hip = split2(d[mt][nt][2], d[mt][nt][3], lop);
                *(uint32_t*)(Oh + o1) = hip;
                *(uint32_t*)(Ol + o1) = lop;
            }
        }
    }
#undef ISSUE_CHUNK
}

// ---------------------------------------------------------------------------
// RMSNorm + RoPE(table) + bf16 split + head-major store. 2 rows per block.
// ---------------------------------------------------------------------------
__global__ __launch_bounds__(256)
void norm_rope_split(const float* __restrict__ in,
                     const float* __restrict__ q_scale, const float* __restrict__ k_scale,
                     __nv_bfloat16* __restrict__ qh, __nv_bfloat16* __restrict__ ql,
                     __nv_bfloat16* __restrict__ kh, __nv_bfloat16* __restrict__ kl) {
    int row = blockIdx.x * 2 + (threadIdx.x >> 7);
    const bool is_q = row < Mrows * Nn;
    const int heads = is_q ? Nn : Kk;
    const int col0  = is_q ? 0 : 2048;
    const float post_scale = is_q ? SCALEf : 1.0f;
    const float* scale = is_q ? q_scale : k_scale;
    __nv_bfloat16* outhi = is_q ? qh : kh;
    __nv_bfloat16* outlo = is_q ? ql : kl;
    if (!is_q) row -= Mrows * Nn;

    const int h    = threadIdx.x & 127;
    const int sub  = threadIdx.x >> 7;
    const int trow = row / heads;
    const int n    = row - trow * heads;
    const int b    = trow >> 11;
    const int t    = trow & 2047;

    float v = in[(size_t)trow * 4096 + col0 + n * Hh + h];
    float ss = v * v;
#pragma unroll
    for (int o = 16; o; o >>= 1) ss += __shfl_xor_sync(0xffffffffu, ss, o);
    __shared__ float warpsum[2][4];
    __shared__ float s_n[2][Hh];
    if ((h & 31) == 0) warpsum[sub][(h >> 5)] = ss;
    __syncthreads();
    float total = warpsum[sub][0] + warpsum[sub][1] + warpsum[sub][2] + warpsum[sub][3];
    float inv_rms = rsqrtf(total * (1.0f / 128.0f) + EPSf);
    s_n[sub][h] = v * inv_rms * scale[h];
    __syncthreads();

    float2 sc = g_rope[(size_t)trow * 64 + (h & 63)];
    float out = (h < 64) ? (s_n[sub][h] * sc.y - s_n[sub][h + 64] * sc.x)
                         : (s_n[sub][h] * sc.y + s_n[sub][h - 64] * sc.x);
    out *= post_scale;
    __nv_bfloat16 hi = __float2bfloat16(out);
    __nv_bfloat16 lo = __float2bfloat16(out - __bfloat162float(hi));
    size_t o = ((size_t)(b * heads + n) * Tt + t) * Hh + h;
    outhi[o] = hi;
    outlo[o] = lo;
}

// ---------------------------------------------------------------------------
// HMMA flash attention, GQA-paired; Q fragments register-resident.
// ---------------------------------------------------------------------------
#define AT_ST0  65536
#define AT_POS  196608
#define AT_SEG  204800
#define AT_META 212992
#define ATT_SMEM (212992 + 512)

__global__ __launch_bounds__(256)
void attn_hmma(const int* __restrict__ seg_g) {
    extern __shared__ char sm[];
    const uint32_t sb = smem_u32(sm);
    int* sPos  = (int*)(sm + AT_POS);
    int* sSeg  = (int*)(sm + AT_SEG);
    int* sKmin = (int*)(sm + AT_META);
    int* sTiles = sKmin + 32;
    int* sCtl   = sTiles + 32;

    const int tid = threadIdx.x, lane = tid & 31, warp = tid >> 5;
    const int qbase = (gridDim.x - 1 - blockIdx.x) * 64;   // longest-first
    const int kvh = blockIdx.y, b = blockIdx.z;
    const int hsel = warp >> 2;
    const int mwarp = warp & 3;
    const int n = kvh * 2 + hsel;

    for (int i = tid; i < 2048; i += 256) {
        sPos[i] = g_pos[b * Tt + i];
        sSeg[i] = seg_g[b * Tt + i];
    }
    for (int i = tid; i < 2048; i += 256) {
        int hh = i >> 10;
        int j = i & 1023;
        int r = j >> 4, u = j & 15;
        uint32_t off = hh * 32768 + ((u >> 3) << 13) + SW128(r * 128 + (u & 7) * 16);
        const char* qh = (const char*)(g_qhh + ((size_t)(b * Nn + kvh * 2 + hh) * Tt + qbase) * Hh);
        const char* ql = (const char*)(g_qhl + ((size_t)(b * Nn + kvh * 2 + hh) * Tt + qbase) * Hh);
        *(uint4*)(sm + off)         = *(const uint4*)(qh + r * 256 + u * 16);
        *(uint4*)(sm + 16384 + off) = *(const uint4*)(ql + r * 256 + u * 16);
    }
    __syncthreads();

    {
#pragma unroll
        for (int j = 0; j < 4; j++) {
            int tt = warp * 4 + j;
            int mn = min(sPos[tt * 64 + lane], sPos[tt * 64 + 32 + lane]);
#pragma unroll
            for (int o = 16; o; o >>= 1) mn = min(mn, __shfl_xor_sync(0xffffffffu, mn, o));
            if (lane == 0) sKmin[tt] = mn;
        }
        if (warp == 0) {
            int v = max(sPos[qbase + lane], sPos[qbase + 32 + lane]);
#pragma unroll
            for (int o = 16; o; o >>= 1) v = max(v, __shfl_xor_sync(0xffffffffu, v, o));
            if (lane == 0) sCtl[0] = v;
        }
    }
    __syncthreads();
    if (tid == 0) {
        int qmax = sCtl[0], na = 0;
        for (int tt = 0; tt < 32; tt++)
            if (sKmin[tt] <= qmax) sTiles[na++] = tt;
        sCtl[1] = na;
    }
    __syncthreads();
    const int nactive = sCtl[1];

    // hoist Q fragments (hi + lo, 8 k-steps) into registers
    const int qrow_l = mwarp * 16 + (lane & 7) + ((lane >> 3) & 1) * 8;
    const int qh_sel = (lane >> 4) << 3;
    const uint32_t qpanel = sb + hsel * 32768;
    uint32_t Qh[8][4], Ql[8][4];
#pragma unroll
    for (int ks = 0; ks < 8; ks++) {
        int hq = ks * 16 + qh_sel;
        uint32_t qoff = ((hq >> 6) << 13) + SW128(qrow_l * 128 + ((hq & 63) << 1));
        LDSM_X4(Qh[ks], qpanel + qoff);
        LDSM_X4(Ql[ks], qpanel + 16384 + qoff);
    }

    const char* kh = (const char*)(g_khh + ((size_t)(b * Kk + kvh) * Tt) * Hh);
    const char* kl = (const char*)(g_khl + ((size_t)(b * Kk + kvh) * Tt) * Hh);
    const char* vh = (const char*)(g_vhh + ((size_t)(b * Kk + kvh) * Tt) * Hh);
    const char* vl = (const char*)(g_vhl + ((size_t)(b * Kk + kvh) * Tt) * Hh);

#define AT_ISSUE(tt, st) do {                                                \
    const int sbase_ = (tt) * 64;                                            \
    uint32_t stb = sb + AT_ST0 + (st) * 65536;                               \
    for (int i = tid; i < 1024; i += 256) {                                  \
        int r = i >> 4, u = i & 15;                                          \
        uint32_t off = ((u >> 3) << 13) + SW128(r * 128 + (u & 7) * 16);     \
        size_t go = (size_t)(sbase_ + r) * 256 + u * 16;                     \
        CP_ASYNC16(stb + off,         kh + go);                              \
        CP_ASYNC16(stb + 16384 + off, kl + go);                              \
        CP_ASYNC16(stb + 32768 + off, vh + go);                              \
        CP_ASYNC16(stb + 49152 + off, vl + go);                              \
    }                                                                        \
} while (0)

    const int r_lo = mwarp * 16 + (lane >> 2);
    const int qp0 = sPos[qbase + r_lo];
    const int qp1 = sPos[qbase + r_lo + 8];
    const int qs0 = sSeg[qbase + r_lo];
    const int qs1 = sSeg[qbase + r_lo + 8];

    float d_o[16][4];
#pragma unroll
    for (int nt = 0; nt < 16; nt++)
#pragma unroll
        for (int j = 0; j < 4; j++) d_o[nt][j] = 0.f;
    float m0 = -1e30f, m1 = -1e30f, l0 = 0.f, l1 = 0.f;

    const int krow_l = ((lane >> 4) & 1) * 8 + (lane & 7);
    const int vrow_l = (((lane >> 3) & 1) << 3) + (lane & 7);
    const int kh_sel = ((lane >> 3) & 1) << 3;
    const int vh_sel = (lane >> 4) << 3;

    if (nactive > 0) { AT_ISSUE(sTiles[0], 0); CP_COMMIT(); }

    for (int j = 0; j < nactive; j++) {
        const int tt = sTiles[j];
        const int sbase = tt * 64;
        if (j + 1 < nactive) { AT_ISSUE(sTiles[j + 1], (j + 1) & 1); CP_COMMIT(); CP_WAIT(1); }
        else                 { CP_WAIT(0); }
        __syncthreads();

        const uint32_t stb = sb + AT_ST0 + (j & 1) * 65536;

        float ds[8][4];
#pragma unroll
        for (int nt = 0; nt < 8; nt++)
#pragma unroll
            for (int jj = 0; jj < 4; jj++) ds[nt][jj] = 0.f;

#pragma unroll
        for (int ks = 0; ks < 8; ks++) {
            int hk = ks * 16 + kh_sel;
            uint32_t kpan = ((hk >> 6) << 13);
            uint32_t kcol = (hk & 63) << 1;
#pragma unroll
            for (int np = 0; np < 4; np++) {
                uint32_t addr = stb + kpan + SW128((np * 16 + krow_l) * 128 + kcol);
                uint32_t tH[4], tL[4];
                LDSM_X4(tH, addr);
                LDSM_X4(tL, addr + 16384);
                MMA16816(ds[2*np],   Qh[ks], tH[0], tH[1]);
                MMA16816(ds[2*np],   Qh[ks], tL[0], tL[1]);
                MMA16816(ds[2*np],   Ql[ks], tH[0], tH[1]);
                MMA16816(ds[2*np+1], Qh[ks], tH[2], tH[3]);
                MMA16816(ds[2*np+1], Qh[ks], tL[2], tL[3]);
                MMA16816(ds[2*np+1], Ql[ks], tH[2], tH[3]);
            }
        }

#pragma unroll
        for (int nt = 0; nt < 8; nt++) {
            int c = sbase + nt * 8 + (lane & 3) * 2;
            int kp0 = sPos[c], kp1 = sPos[c + 1];
            int ks0 = sSeg[c], ks1 = sSeg[c + 1];
            if (!(kp0 <= qp0 && ks0 == qs0)) ds[nt][0] = -1e30f;
            if (!(kp1 <= qp0 && ks1 == qs0)) ds[nt][1] = -1e30f;
            if (!(kp0 <= qp1 && ks0 == qs1)) ds[nt][2] = -1e30f;
            if (!(kp1 <= qp1 && ks1 == qs1)) ds[nt][3] = -1e30f;
        }

        float tm0 = -1e30f, tm1 = -1e30f;
#pragma unroll
        for (int nt = 0; nt < 8; nt++) {
            tm0 = fmaxf(tm0, fmaxf(ds[nt][0], ds[nt][1]));
            tm1 = fmaxf(tm1, fmaxf(ds[nt][2], ds[nt][3]));
        }
        tm0 = fmaxf(tm0, __shfl_xor_sync(0xffffffffu, tm0, 1));
        tm0 = fmaxf(tm0, __shfl_xor_sync(0xffffffffu, tm0, 2));
        tm1 = fmaxf(tm1, __shfl_xor_sync(0xffffffffu, tm1, 1));
        tm1 = fmaxf(tm1, __shfl_xor_sync(0xffffffffu, tm1, 2));
        float nm0 = fmaxf(m0, tm0), nm1 = fmaxf(m1, tm1);
        float a0 = __expf(m0 - nm0), a1 = __expf(m1 - nm1);
        float gg0 = (nm0 > -0.9e30f) ? 1.f : 0.f;
        float gg1 = (nm1 > -0.9e30f) ? 1.f : 0.f;
        float s0 = 0.f, s1 = 0.f;
#pragma unroll
        for (int nt = 0; nt < 8; nt++) {
            ds[nt][0] = gg0 * __expf(ds[nt][0] - nm0);
            ds[nt][1] = gg0 * __expf(ds[nt][1] - nm0);
            ds[nt][2] = gg1 * __expf(ds[nt][2] - nm1);
            ds[nt][3] = gg1 * __expf(ds[nt][3] - nm1);
            s0 += ds[nt][0] + ds[nt][1];
            s1 += ds[nt][2] + ds[nt][3];
        }
        s0 += __shfl_xor_sync(0xffffffffu, s0, 1);
        s0 += __shfl_xor_sync(0xffffffffu, s0, 2);
        s1 += __shfl_xor_sync(0xffffffffu, s1, 1);
        s1 += __shfl_xor_sync(0xffffffffu, s1, 2);
        l0 = l0 * a0 + s0; m0 = nm0;
        l1 = l1 * a1 + s1; m1 = nm1;
#pragma unroll
        for (int nt = 0; nt < 16; nt++) {
            d_o[nt][0] *= a0; d_o[nt][1] *= a0;
            d_o[nt][2] *= a1; d_o[nt][3] *= a1;
        }

        uint32_t Ph[4][4], Pl[4][4];
#pragma unroll
        for (int kb = 0; kb < 4; kb++) {
            Ph[kb][0] = split2(ds[2*kb][0],   ds[2*kb][1],   Pl[kb][0]);
            Ph[kb][1] = split2(ds[2*kb][2],   ds[2*kb][3],   Pl[kb][1]);
            Ph[kb][2] = split2(ds[2*kb+1][0], ds[2*kb+1][1], Pl[kb][2]);
            Ph[kb][3] = split2(ds[2*kb+1][2], ds[2*kb+1][3], Pl[kb][3]);
        }

#pragma unroll
        for (int ntp = 0; ntp < 8; ntp++) {
            int hv = ntp * 16 + vh_sel;
            uint32_t vpan = ((hv >> 6) << 13);
            uint32_t vcol = (hv & 63) << 1;
#pragma unroll
            for (int kb = 0; kb < 4; kb++) {
                uint32_t addr = stb + 32768 + vpan + SW128((kb * 16 + vrow_l) * 128 + vcol);
                uint32_t tH[4], tL[4];
                LDSM_X4_T(tH, addr);
                LDSM_X4_T(tL, addr + 16384);
                MMA16816(d_o[2*ntp],   Ph[kb], tH[0], tH[1]);
                MMA16816(d_o[2*ntp],   Pl[kb], tH[0], tH[1]);
                MMA16816(d_o[2*ntp],   Ph[kb], tL[0], tL[1]);
                MMA16816(d_o[2*ntp+1], Ph[kb], tH[2], tH[3]);
                MMA16816(d_o[2*ntp+1], Pl[kb], tH[2], tH[3]);
                MMA16816(d_o[2*ntp+1], Ph[kb], tL[2], tL[3]);
            }
        }
        __syncthreads();
    }
#undef AT_ISSUE

    float il0 = (l0 > 0.f) ? (1.f / l0) : 0.f;
    float il1 = (l1 > 0.f) ? (1.f / l1) : 0.f;
    size_t base0 = ((size_t)(b * Tt + qbase + r_lo))     * 2048 + n * 128;
    size_t base1 = ((size_t)(b * Tt + qbase + r_lo + 8)) * 2048 + n * 128;
#pragma unroll
    for (int nt = 0; nt < 16; nt++) {
        int h = nt * 8 + (lane & 3) * 2;
        uint32_t lop;
        uint32_t hip = split2(d_o[nt][0] * il0, d_o[nt][1] * il0, lop);
        *(uint32_t*)(g_atthi + base0 + h) = hip;
        *(uint32_t*)(g_attlo + base0 + h) = lop;
        hip = split2(d_o[nt][2] * il1, d_o[nt][3] * il1, lop);
        *(uint32_t*)(g_atthi + base1 + h) = hip;
        *(uint32_t*)(g_attlo + base1 + h) = lop;
    }
}

// ---------------------------------------------------------------------------
extern "C" void kernel_launch(void* const* d_in, const int* in_sizes, int n_in,
                              void* d_out, int out_size) {
    const float* x       = (const float*)d_in[0];
    const int*   seg     = (const int*)  d_in[1];
    const float* wq      = (const float*)d_in[2];
    const float* wk      = (const float*)d_in[3];
    const float* wv      = (const float*)d_in[4];
    const float* wo      = (const float*)d_in[5];
    const float* q_scale = (const float*)d_in[6];
    const float* k_scale = (const float*)d_in[7];
    float* out = (float*)d_out;

    float* qkv;
    cudaGetSymbolAddress((void**)&qkv, g_qkv);
    __nv_bfloat16 *xhi, *xlo, *ahi, *alo;
    __nv_bfloat16 *wch, *wcl, *woh, *wol;
    __nv_bfloat16 *qhh, *qhl, *khh, *khl, *vhh, *vhl;
    cudaGetSymbolAddress((void**)&xhi, g_xhi);
    cudaGetSymbolAddress((void**)&xlo, g_xlo);
    cudaGetSymbolAddress((void**)&ahi, g_atthi);
    cudaGetSymbolAddress((void**)&alo, g_attlo);
    cudaGetSymbolAddress((void**)&wch, g_wqkvT_hi);
    cudaGetSymbolAddress((void**)&wcl, g_wqkvT_lo);
    cudaGetSymbolAddress((void**)&woh, g_woT_hi);
    cudaGetSymbolAddress((void**)&wol, g_woT_lo);
    cudaGetSymbolAddress((void**)&qhh, g_qhh);
    cudaGetSymbolAddress((void**)&qhl, g_qhl);
    cudaGetSymbolAddress((void**)&khh, g_khh);
    cudaGetSymbolAddress((void**)&khl, g_khl);
    cudaGetSymbolAddress((void**)&vhh, g_vhh);
    cudaGetSymbolAddress((void**)&vhl, g_vhl);

    cudaFuncSetAttribute(gemm_hmma, cudaFuncAttributeMaxDynamicSharedMemorySize,
                         GEMM_SMEM);
    cudaFuncSetAttribute(attn_hmma, cudaFuncAttributeMaxDynamicSharedMemorySize,
                         ATT_SMEM);

    pos_kernel<<<Bb, 256>>>(seg);
    rope_kernel<<<Mrows * 64 / 256, 256>>>();

    // single unified conversion launch (x + all weights)
    conv_all<<<7168, 256>>>(x, wq, wk, wv, wo);

    // Combined QKV projection: q|k fp32 -> g_qkv, v -> split head-major
    gemm_hmma<<<dim3(32, Mrows / 256), 256, GEMM_SMEM>>>(
        xhi, xlo, wch, wcl, qkv, vhh, vhl, 3, 4096, 1024);

    // RMSNorm + RoPE(table) + split (q and k, 2 rows/block)
    norm_rope_split<<<Mrows * (Nn + Kk) / 2, 256>>>(
        qkv, q_scale, k_scale, qhh, qhl, khh, khl);

    // HMMA flash attention (GQA-paired, Q register-resident, longest-first)
    attn_hmma<<<dim3(Tt / 64, Kk, Bb), 256, ATT_SMEM>>>(seg);

    // output projection (fp32 store to d_out) — 128 CTAs = single wave
    gemm_hmma<<<dim3(1024 / 128, Mrows / 256), 256, GEMM_SMEM>>>(
        ahi, alo, woh, wol, out, (__nv_bfloat16*)0, (__nv_bfloat16*)0, 0, 1024, 2048);
}

// round 16
// speedup vs baseline: 1.0021x; 1.0021x over previous
#include <cuda_runtime.h>
#include <cuda_bf16.h>
#include <math.h>
#include <float.h>
#include <limits.h>
#include <stdint.h>

// Problem constants
#define Bb 2
#define Tt 2048
#define Dd 1024
#define Nn 16
#define Kk 8
#define Hh 128
#define Gg 2
#define Mrows (Bb*Tt)          // 4096

static constexpr float EPSf   = 1e-6f;
static constexpr float LOG_THETA = 13.815510557964274f;  // ln(1e6)
static constexpr float SCALEf = 0.08838834764831845f;    // 128^-0.5

// ---------------------------------------------------------------------------
// Scratch (allocation-free rule: __device__ globals)
// ---------------------------------------------------------------------------
__device__ int    g_pos[Mrows];
__device__ float2 g_rope[(size_t)Mrows * 64];
__device__ float  g_qkv[(size_t)Mrows * 4096];

__device__ __nv_bfloat16 g_xhi[(size_t)Mrows * Dd];
__device__ __nv_bfloat16 g_xlo[(size_t)Mrows * Dd];
__device__ __nv_bfloat16 g_atthi[(size_t)Mrows * Nn * Hh];
__device__ __nv_bfloat16 g_attlo[(size_t)Mrows * Nn * Hh];
__device__ __nv_bfloat16 g_wqkvT_hi[(size_t)4096 * Dd];
__device__ __nv_bfloat16 g_wqkvT_lo[(size_t)4096 * Dd];
__device__ __nv_bfloat16 g_woT_hi[(size_t)Dd * (Nn*Hh)];
__device__ __nv_bfloat16 g_woT_lo[(size_t)Dd * (Nn*Hh)];

__device__ __nv_bfloat16 g_qhh[(size_t)Bb * Nn * Tt * Hh];
__device__ __nv_bfloat16 g_qhl[(size_t)Bb * Nn * Tt * Hh];
__device__ __nv_bfloat16 g_khh[(size_t)Bb * Kk * Tt * Hh];
__device__ __nv_bfloat16 g_khl[(size_t)Bb * Kk * Tt * Hh];
__device__ __nv_bfloat16 g_vhh[(size_t)Bb * Kk * Tt * Hh];
__device__ __nv_bfloat16 g_vhl[(size_t)Bb * Kk * Tt * Hh];

// ---------------------------------------------------------------------------
// PTX helpers
// ---------------------------------------------------------------------------
__device__ __forceinline__ uint32_t smem_u32(const void* p) {
    uint32_t a;
    asm("{ .reg .u64 t; cvta.to.shared.u64 t, %1; cvt.u32.u64 %0, t; }"
        : "=r"(a) : "l"(p));
    return a;
}
#define SW128(off) ((off) ^ (((off) >> 3) & 0x70))

#define CP_ASYNC16(saddr, gaddr) \
    asm volatile("cp.async.cg.shared.global [%0], [%1], 16;" \
        :: "r"(saddr), "l"(gaddr) : "memory")
#define CP_COMMIT() asm volatile("cp.async.commit_group;" ::: "memory")
#define CP_WAIT(n)  asm volatile("cp.async.wait_group %0;" :: "n"(n) : "memory")

#define LDSM_X4(r, addr) \
    asm volatile("ldmatrix.sync.aligned.m8n8.x4.shared.b16 {%0,%1,%2,%3}, [%4];" \
        : "=r"((r)[0]), "=r"((r)[1]), "=r"((r)[2]), "=r"((r)[3]) : "r"(addr))
#define LDSM_X4_T(r, addr) \
    asm volatile("ldmatrix.sync.aligned.m8n8.x4.trans.shared.b16 {%0,%1,%2,%3}, [%4];" \
        : "=r"((r)[0]), "=r"((r)[1]), "=r"((r)[2]), "=r"((r)[3]) : "r"(addr))

// NOTE: not volatile — pure register op, let ptxas schedule/interleave.
#define MMA16816(d, a, b0r, b1r) \
    asm("mma.sync.aligned.m16n8k16.row.col.f32.bf16.bf16.f32 " \
        "{%0,%1,%2,%3}, {%4,%5,%6,%7}, {%8,%9}, {%0,%1,%2,%3};" \
        : "+f"((d)[0]), "+f"((d)[1]), "+f"((d)[2]), "+f"((d)[3]) \
        : "r"((a)[0]), "r"((a)[1]), "r"((a)[2]), "r"((a)[3]), \
          "r"((b0r)), "r"((b1r)))

__device__ __forceinline__ uint32_t split2(float x0, float x1, uint32_t& lopack) {
    __nv_bfloat16 h0 = __float2bfloat16(x0), h1 = __float2bfloat16(x1);
    float r0 = x0 - __bfloat162float(h0), r1 = x1 - __bfloat162float(h1);
    __nv_bfloat16 g0 = __float2bfloat16(r0), g1 = __float2bfloat16(r1);
    lopack = (uint32_t)__bfloat16_as_ushort(g0) | ((uint32_t)__bfloat16_as_ushort(g1) << 16);
    return (uint32_t)__bfloat16_as_ushort(h0) | ((uint32_t)__bfloat16_as_ushort(h1) << 16);
}

// ---------------------------------------------------------------------------
// positions_from_segment_ids
// ---------------------------------------------------------------------------
__global__ void pos_kernel(const int* __restrict__ seg) {
    int b = blockIdx.x;
    int tid = threadIdx.x;
    __shared__ int sv[256], si[256];
    int bv = INT_MIN, bi = INT_MAX;
    for (int t = tid; t < Tt; t += 256) {
        int v = seg[b * Tt + t];
        if (v > bv) { bv = v; bi = t; }
    }
    sv[tid] = bv; si[tid] = bi;
    __syncthreads();
    for (int o = 128; o; o >>= 1) {
        if (tid < o) {
            if (sv[tid + o] > sv[tid] ||
                (sv[tid + o] == sv[tid] && si[tid + o] < si[tid])) {
                sv[tid] = sv[tid + o]; si[tid] = si[tid + o];
            }
        }
        __syncthreads();
    }
    int off = si[0];
    for (int t = tid; t < Tt; t += 256) {
        int v = seg[b * Tt + t];
        g_pos[b * Tt + t] = (v != 0) ? (t - off) : (1 << 30);
    }
}

// ---------------------------------------------------------------------------
// RoPE sin/cos table
// ---------------------------------------------------------------------------
__global__ __launch_bounds__(256)
void rope_kernel() {
    int idx = blockIdx.x * 256 + threadIdx.x;
    int gr = idx >> 6, i = idx & 63;
    int pos = g_pos[gr];
    float inv_freq = __expf(-(float)i * (LOG_THETA / 64.0f));
    float ang = (float)pos * inv_freq;
    g_rope[idx] = make_float2(sinf(ang), cosf(ang));
}

// ---------------------------------------------------------------------------
// Unified conversion kernel (7168 blocks; ranges as R14)
// ---------------------------------------------------------------------------
__global__ __launch_bounds__(256)
void conv_all(const float* __restrict__ x,
              const float* __restrict__ wq, const float* __restrict__ wk,
              const float* __restrict__ wv, const float* __restrict__ wo) {
    int blk = blockIdx.x;
    if (blk < 1024) {
        size_t i = (size_t)blk * 1024 + threadIdx.x;
#pragma unroll
        for (int it = 0; it < 4; it++, i += 256) {
            float4 v = ((const float4*)x)[i];
            uint32_t l01, l23;
            uint32_t h01 = split2(v.x, v.y, l01);
            uint32_t h23 = split2(v.z, v.w, l23);
            ((uint2*)g_xhi)[i] = make_uint2(h01, h23);
            ((uint2*)g_xlo)[i] = make_uint2(l01, l23);
        }
        return;
    }
    const float* w; __nv_bfloat16 *hi, *lo;
    int Nc, nblk_x, row_off, dstld;
    if (blk < 3072)      { blk -= 1024; w = wq; Nc = 2048; nblk_x = 64; row_off = 0;
                           dstld = 1024; hi = g_wqkvT_hi; lo = g_wqkvT_lo; }
    else if (blk < 4096) { blk -= 3072; w = wk; Nc = 1024; nblk_x = 32; row_off = 2048;
                           dstld = 1024; hi = g_wqkvT_hi; lo = g_wqkvT_lo; }
    else if (blk < 5120) { blk -= 4096; w = wv; Nc = 1024; nblk_x = 32; row_off = 3072;
                           dstld = 1024; hi = g_wqkvT_hi; lo = g_wqkvT_lo; }
    else                 { blk -= 5120; w = wo; Nc = 1024; nblk_x = 32; row_off = 0;
                           dstld = 2048; hi = g_woT_hi; lo = g_woT_lo; }
    int bx = blk % nblk_x, by = blk / nblk_x;
    int n0 = bx * 32, k0 = by * 32;
    int tx = threadIdx.x & 31, ty = threadIdx.x >> 5;
    __shared__ float t[32][33];
    for (int i = ty; i < 32; i += 8)
        t[i][tx] = w[(size_t)(k0 + i) * Nc + n0 + tx];
    __syncthreads();
    for (int i = ty; i < 32; i += 8) {
        float v = t[tx][i];
        __nv_bfloat16 h = __float2bfloat16(v);
        __nv_bfloat16 l = __float2bfloat16(v - __bfloat162float(h));
        size_t o = (size_t)(row_off + n0 + i) * dstld + k0 + tx;
        hi[o] = h; lo[o] = l;
    }
}

// ---------------------------------------------------------------------------
// HMMA bf16-split GEMM, 256x128 tile, pass-structured MMA issue.
// ---------------------------------------------------------------------------
#define GSTAGE  98304
#define GA_LO   32768
#define GB_HI   65536
#define GB_LO   81920
#define GEMM_SMEM (2 * GSTAGE)

__global__ __launch_bounds__(256)
void gemm_hmma(const __nv_bfloat16* __restrict__ Ahi, const __nv_bfloat16* __restrict__ Alo,
               const __nv_bfloat16* __restrict__ Bhi, const __nv_bfloat16* __restrict__ Blo,
               float* __restrict__ C,
               __nv_bfloat16* __restrict__ Oh, __nv_bfloat16* __restrict__ Ol,
               int mode, int Nc, int Kd) {
    extern __shared__ char smc[];
    const int tid  = threadIdx.x;
    const int lane = tid & 31;
    const int wid  = tid >> 5;
    const int warp_m = wid & 3;
    const int warp_n = wid >> 2;
    const int m0 = blockIdx.y * 256, n0 = blockIdx.x * 128;

    const int u = tid & 7;
    const int r = tid >> 3;

    const uint32_t sbase = smem_u32(smc);
    const int nchunk = Kd >> 6;

    float d[4][8][4];
#pragma unroll
    for (int mt = 0; mt < 4; mt++)
#pragma unroll
        for (int nt = 0; nt < 8; nt++)
#pragma unroll
            for (int j = 0; j < 4; j++) d[mt][nt][j] = 0.f;

#define ISSUE_CHUNK(c, s) do {                                               \
    const int k0e = (c) * 64;                                                \
    uint32_t sa = sbase + (s) * GSTAGE;                                      \
    _Pragma("unroll")                                                        \
    for (int i = 0; i < 8; i++) {                                            \
        int row = r + i * 32;                                                \
        uint32_t so = SW128(row * 128 + u * 16);                             \
        CP_ASYNC16(sa + so,         Ahi + (size_t)(m0 + row) * Kd + k0e + u * 8); \
        CP_ASYNC16(sa + GA_LO + so, Alo + (size_t)(m0 + row) * Kd + k0e + u * 8); \
    }                                                                        \
    _Pragma("unroll")                                                        \
    for (int i = 0; i < 4; i++) {                                            \
        int row = r + i * 32;                                                \
        uint32_t so = SW128(row * 128 + u * 16);                             \
        CP_ASYNC16(sa + GB_HI + so, Bhi + (size_t)(n0 + row) * Kd + k0e + u * 8); \
        CP_ASYNC16(sa + GB_LO + so, Blo + (size_t)(n0 + row) * Kd + k0e + u * 8); \
    }                                                                        \
} while (0)

    ISSUE_CHUNK(0, 0);
    CP_COMMIT();

    for (int c = 0; c < nchunk; c++) {
        if (c + 1 < nchunk) { ISSUE_CHUNK(c + 1, (c + 1) & 1); CP_COMMIT(); CP_WAIT(1); }
        else                { CP_WAIT(0); }
        __syncthreads();

        const uint32_t sb = sbase + (c & 1) * GSTAGE;
#pragma unroll
        for (int s = 0; s < 4; s++) {
            uint32_t bH[8][2], bL[8][2];
#pragma unroll
            for (int np = 0; np < 4; np++) {
                int row  = warp_n * 64 + np * 16 + ((lane >> 4) & 1) * 8 + (lane & 7);
                int unit = s * 2 + ((lane >> 3) & 1);
                uint32_t addr = sb + GB_HI + SW128(row * 128 + unit * 16);
                uint32_t tmp[4];
                LDSM_X4(tmp, addr);
                bH[2*np][0] = tmp[0]; bH[2*np][1] = tmp[1];
                bH[2*np+1][0] = tmp[2]; bH[2*np+1][1] = tmp[3];
                LDSM_X4(tmp, addr + 16384);
                bL[2*np][0] = tmp[0]; bL[2*np][1] = tmp[1];
                bL[2*np+1][0] = tmp[2]; bL[2*np+1][1] = tmp[3];
            }
#pragma unroll
            for (int mt = 0; mt < 4; mt++) {
                uint32_t aH[4], aL[4];
                int row  = warp_m * 64 + mt * 16 + (lane & 7) + ((lane >> 3) & 1) * 8;
                int unit = s * 2 + (lane >> 4);
                uint32_t addr = sb + SW128(row * 128 + unit * 16);
                LDSM_X4(aH, addr);
                LDSM_X4(aL, addr + GA_LO);
                // pass-structured: same-accumulator reuse distance = 8
#pragma unroll
                for (int nt = 0; nt < 8; nt++)
                    MMA16816(d[mt][nt], aH, bH[nt][0], bH[nt][1]);
#pragma unroll
                for (int nt = 0; nt < 8; nt++)
                    MMA16816(d[mt][nt], aH, bL[nt][0], bL[nt][1]);
#pragma unroll
                for (int nt = 0; nt < 8; nt++)
                    MMA16816(d[mt][nt], aL, bH[nt][0], bH[nt][1]);
            }
        }
        __syncthreads();
    }

    const bool vstore = (mode == 3) && (blockIdx.x >= 24);
    if (!vstore) {
#pragma unroll
        for (int mt = 0; mt < 4; mt++) {
#pragma unroll
            for (int nt = 0; nt < 8; nt++) {
                int row = m0 + warp_m * 64 + mt * 16 + (lane >> 2);
                int col = n0 + warp_n * 64 + nt * 8 + (lane & 3) * 2;
                *(float2*)&C[(size_t)row * Nc + col] =
                    make_float2(d[mt][nt][0], d[mt][nt][1]);
                *(float2*)&C[(size_t)(row + 8) * Nc + col] =
                    make_float2(d[mt][nt][2], d[mt][nt][3]);
            }
        }
    } else {
#pragma unroll
        for (int mt = 0; mt < 4; mt++) {
#pragma unroll
            for (int nt = 0; nt < 8; nt++) {
                int row = m0 + warp_m * 64 + mt * 16 + (lane >> 2);
                int col = n0 - 3072 + warp_n * 64 + nt * 8 + (lane & 3) * 2;
                int bq = row >> 11, t = row & 2047;
                int kv = col >> 7, h = col & 127;
                size_t o0 = ((size_t)(bq * Kk + kv) * Tt + t) * Hh + h;
                size_t o1 = ((size_t)(bq * Kk + kv) * Tt + t + 8) * Hh + h;
                uint32_t lop;
                uint32_t hip = split2(d[mt][nt][0], d[mt][nt][1], lop);
                *(uint32_t*)(Oh + o0) = hip;
                *(uint32_t*)(Ol + o0) = lop;
                hip = split2(d[mt][nt][2], d[mt][nt][3], lop);
                *(uint32_t*)(Oh + o1) = hip;
                *(uint32_t*)(Ol + o1) = lop;
            }
        }
    }
#undef ISSUE_CHUNK
}

// ---------------------------------------------------------------------------
// RMSNorm + RoPE(table) + bf16 split + head-major store. 2 rows per block.
// ---------------------------------------------------------------------------
__global__ __launch_bounds__(256)
void norm_rope_split(const float* __restrict__ in,
                     const float* __restrict__ q_scale, const float* __restrict__ k_scale,
                     __nv_bfloat16* __restrict__ qh, __nv_bfloat16* __restrict__ ql,
                     __nv_bfloat16* __restrict__ kh, __nv_bfloat16* __restrict__ kl) {
    int row = blockIdx.x * 2 + (threadIdx.x >> 7);
    const bool is_q = row < Mrows * Nn;
    const int heads = is_q ? Nn : Kk;
    const int col0  = is_q ? 0 : 2048;
    const float post_scale = is_q ? SCALEf : 1.0f;
    const float* scale = is_q ? q_scale : k_scale;
    __nv_bfloat16* outhi = is_q ? qh : kh;
    __nv_bfloat16* outlo = is_q ? ql : kl;
    if (!is_q) row -= Mrows * Nn;

    const int h    = threadIdx.x & 127;
    const int sub  = threadIdx.x >> 7;
    const int trow = row / heads;
    const int n    = row - trow * heads;
    const int b    = trow >> 11;
    const int t    = trow & 2047;

    float v = in[(size_t)trow * 4096 + col0 + n * Hh + h];
    float ss = v * v;
#pragma unroll
    for (int o = 16; o; o >>= 1) ss += __shfl_xor_sync(0xffffffffu, ss, o);
    __shared__ float warpsum[2][4];
    __shared__ float s_n[2][Hh];
    if ((h & 31) == 0) warpsum[sub][(h >> 5)] = ss;
    __syncthreads();
    float total = warpsum[sub][0] + warpsum[sub][1] + warpsum[sub][2] + warpsum[sub][3];
    float inv_rms = rsqrtf(total * (1.0f / 128.0f) + EPSf);
    s_n[sub][h] = v * inv_rms * scale[h];
    __syncthreads();

    float2 sc = g_rope[(size_t)trow * 64 + (h & 63)];
    float out = (h < 64) ? (s_n[sub][h] * sc.y - s_n[sub][h + 64] * sc.x)
                         : (s_n[sub][h] * sc.y + s_n[sub][h - 64] * sc.x);
    out *= post_scale;
    __nv_bfloat16 hi = __float2bfloat16(out);
    __nv_bfloat16 lo = __float2bfloat16(out - __bfloat162float(hi));
    size_t o = ((size_t)(b * heads + n) * Tt + t) * Hh + h;
    outhi[o] = hi;
    outlo[o] = lo;
}

// ---------------------------------------------------------------------------
// HMMA flash attention, GQA-paired; Q register-resident; pass-structured MMAs.
// ---------------------------------------------------------------------------
#define AT_ST0  65536
#define AT_POS  196608
#define AT_SEG  204800
#define AT_META 212992
#define ATT_SMEM (212992 + 512)

__global__ __launch_bounds__(256)
void attn_hmma(const int* __restrict__ seg_g) {
    extern __shared__ char sm[];
    const uint32_t sb = smem_u32(sm);
    int* sPos  = (int*)(sm + AT_POS);
    int* sSeg  = (int*)(sm + AT_SEG);
    int* sKmin = (int*)(sm + AT_META);
    int* sTiles = sKmin + 32;
    int* sCtl   = sTiles + 32;

    const int tid = threadIdx.x, lane = tid & 31, warp = tid >> 5;
    const int qbase = (gridDim.x - 1 - blockIdx.x) * 64;   // longest-first
    const int kvh = blockIdx.y, b = blockIdx.z;
    const int hsel = warp >> 2;
    const int mwarp = warp & 3;
    const int n = kvh * 2 + hsel;

    for (int i = tid; i < 2048; i += 256) {
        sPos[i] = g_pos[b * Tt + i];
        sSeg[i] = seg_g[b * Tt + i];
    }
    for (int i = tid; i < 2048; i += 256) {
        int hh = i >> 10;
        int j = i & 1023;
        int r = j >> 4, u = j & 15;
        uint32_t off = hh * 32768 + ((u >> 3) << 13) + SW128(r * 128 + (u & 7) * 16);
        const char* qh = (const char*)(g_qhh + ((size_t)(b * Nn + kvh * 2 + hh) * Tt + qbase) * Hh);
        const char* ql = (const char*)(g_qhl + ((size_t)(b * Nn + kvh * 2 + hh) * Tt + qbase) * Hh);
        *(uint4*)(sm + off)         = *(const uint4*)(qh + r * 256 + u * 16);
        *(uint4*)(sm + 16384 + off) = *(const uint4*)(ql + r * 256 + u * 16);
    }
    __syncthreads();

    {
#pragma unroll
        for (int j = 0; j < 4; j++) {
            int tt = warp * 4 + j;
            int mn = min(sPos[tt * 64 + lane], sPos[tt * 64 + 32 + lane]);
#pragma unroll
            for (int o = 16; o; o >>= 1) mn = min(mn, __shfl_xor_sync(0xffffffffu, mn, o));
            if (lane == 0) sKmin[tt] = mn;
        }
        if (warp == 0) {
            int v = max(sPos[qbase + lane], sPos[qbase + 32 + lane]);
#pragma unroll
            for (int o = 16; o; o >>= 1) v = max(v, __shfl_xor_sync(0xffffffffu, v, o));
            if (lane == 0) sCtl[0] = v;
        }
    }
    __syncthreads();
    if (tid == 0) {
        int qmax = sCtl[0], na = 0;
        for (int tt = 0; tt < 32; tt++)
            if (sKmin[tt] <= qmax) sTiles[na++] = tt;
        sCtl[1] = na;
    }
    __syncthreads();
    const int nactive = sCtl[1];

    // hoist Q fragments into registers
    const int qrow_l = mwarp * 16 + (lane & 7) + ((lane >> 3) & 1) * 8;
    const int qh_sel = (lane >> 4) << 3;
    const uint32_t qpanel = sb + hsel * 32768;
    uint32_t Qh[8][4], Ql[8][4];
#pragma unroll
    for (int ks = 0; ks < 8; ks++) {
        int hq = ks * 16 + qh_sel;
        uint32_t qoff = ((hq >> 6) << 13) + SW128(qrow_l * 128 + ((hq & 63) << 1));
        LDSM_X4(Qh[ks], qpanel + qoff);
        LDSM_X4(Ql[ks], qpanel + 16384 + qoff);
    }

    const char* kh = (const char*)(g_khh + ((size_t)(b * Kk + kvh) * Tt) * Hh);
    const char* kl = (const char*)(g_khl + ((size_t)(b * Kk + kvh) * Tt) * Hh);
    const char* vh = (const char*)(g_vhh + ((size_t)(b * Kk + kvh) * Tt) * Hh);
    const char* vl = (const char*)(g_vhl + ((size_t)(b * Kk + kvh) * Tt) * Hh);

#define AT_ISSUE(tt, st) do {                                                \
    const int sbase_ = (tt) * 64;                                            \
    uint32_t stb = sb + AT_ST0 + (st) * 65536;                               \
    for (int i = tid; i < 1024; i += 256) {                                  \
        int r = i >> 4, u = i & 15;                                          \
        uint32_t off = ((u >> 3) << 13) + SW128(r * 128 + (u & 7) * 16);     \
        size_t go = (size_t)(sbase_ + r) * 256 + u * 16;                     \
        CP_ASYNC16(stb + off,         kh + go);                              \
        CP_ASYNC16(stb + 16384 + off, kl + go);                              \
        CP_ASYNC16(stb + 32768 + off, vh + go);                              \
        CP_ASYNC16(stb + 49152 + off, vl + go);                              \
    }                                                                        \
} while (0)

    const int r_lo = mwarp * 16 + (lane >> 2);
    const int qp0 = sPos[qbase + r_lo];
    const int qp1 = sPos[qbase + r_lo + 8];
    const int qs0 = sSeg[qbase + r_lo];
    const int qs1 = sSeg[qbase + r_lo + 8];

    float d_o[16][4];
#pragma unroll
    for (int nt = 0; nt < 16; nt++)
#pragma unroll
        for (int j = 0; j < 4; j++) d_o[nt][j] = 0.f;
    float m0 = -1e30f, m1 = -1e30f, l0 = 0.f, l1 = 0.f;

    const int krow_l = ((lane >> 4) & 1) * 8 + (lane & 7);
    const int vrow_l = (((lane >> 3) & 1) << 3) + (lane & 7);
    const int kh_sel = ((lane >> 3) & 1) << 3;
    const int vh_sel = (lane >> 4) << 3;

    if (nactive > 0) { AT_ISSUE(sTiles[0], 0); CP_COMMIT(); }

    for (int j = 0; j < nactive; j++) {
        const int tt = sTiles[j];
        const int sbase = tt * 64;
        if (j + 1 < nactive) { AT_ISSUE(sTiles[j + 1], (j + 1) & 1); CP_COMMIT(); CP_WAIT(1); }
        else                 { CP_WAIT(0); }
        __syncthreads();

        const uint32_t stb = sb + AT_ST0 + (j & 1) * 65536;

        float ds[8][4];
#pragma unroll
        for (int nt = 0; nt < 8; nt++)
#pragma unroll
            for (int jj = 0; jj < 4; jj++) ds[nt][jj] = 0.f;

        // ---- S = Q K^T: np processed in pairs, pass-structured ----
#pragma unroll
        for (int ks = 0; ks < 8; ks++) {
            int hk = ks * 16 + kh_sel;
            uint32_t kpan = ((hk >> 6) << 13);
            uint32_t kcol = (hk & 63) << 1;
#pragma unroll
            for (int p = 0; p < 2; p++) {
                int np0 = 2 * p, np1 = 2 * p + 1;
                uint32_t a0 = stb + kpan + SW128((np0 * 16 + krow_l) * 128 + kcol);
                uint32_t a1 = stb + kpan + SW128((np1 * 16 + krow_l) * 128 + kcol);
                uint32_t tH0[4], tL0[4], tH1[4], tL1[4];
                LDSM_X4(tH0, a0);
                LDSM_X4(tL0, a0 + 16384);
                LDSM_X4(tH1, a1);
                LDSM_X4(tL1, a1 + 16384);
                // pass 1: Qh x hi
                MMA16816(ds[2*np0],   Qh[ks], tH0[0], tH0[1]);
                MMA16816(ds[2*np0+1], Qh[ks], tH0[2], tH0[3]);
                MMA16816(ds[2*np1],   Qh[ks], tH1[0], tH1[1]);
                MMA16816(ds[2*np1+1], Qh[ks], tH1[2], tH1[3]);
                // pass 2: Qh x lo
                MMA16816(ds[2*np0],   Qh[ks], tL0[0], tL0[1]);
                MMA16816(ds[2*np0+1], Qh[ks], tL0[2], tL0[3]);
                MMA16816(ds[2*np1],   Qh[ks], tL1[0], tL1[1]);
                MMA16816(ds[2*np1+1], Qh[ks], tL1[2], tL1[3]);
                // pass 3: Ql x hi
                MMA16816(ds[2*np0],   Ql[ks], tH0[0], tH0[1]);
                MMA16816(ds[2*np0+1], Ql[ks], tH0[2], tH0[3]);
                MMA16816(ds[2*np1],   Ql[ks], tH1[0], tH1[1]);
                MMA16816(ds[2*np1+1], Ql[ks], tH1[2], tH1[3]);
            }
        }

#pragma unroll
        for (int nt = 0; nt < 8; nt++) {
            int c = sbase + nt * 8 + (lane & 3) * 2;
            int kp0 = sPos[c], kp1 = sPos[c + 1];
            int ks0 = sSeg[c], ks1 = sSeg[c + 1];
            if (!(kp0 <= qp0 && ks0 == qs0)) ds[nt][0] = -1e30f;
            if (!(kp1 <= qp0 && ks1 == qs0)) ds[nt][1] = -1e30f;
            if (!(kp0 <= qp1 && ks0 == qs1)) ds[nt][2] = -1e30f;
            if (!(kp1 <= qp1 && ks1 == qs1)) ds[nt][3] = -1e30f;
        }

        float tm0 = -1e30f, tm1 = -1e30f;
#pragma unroll
        for (int nt = 0; nt < 8; nt++) {
            tm0 = fmaxf(tm0, fmaxf(ds[nt][0], ds[nt][1]));
            tm1 = fmaxf(tm1, fmaxf(ds[nt][2], ds[nt][3]));
        }
        tm0 = fmaxf(tm0, __shfl_xor_sync(0xffffffffu, tm0, 1));
        tm0 = fmaxf(tm0, __shfl_xor_sync(0xffffffffu, tm0, 2));
        tm1 = fmaxf(tm1, __shfl_xor_sync(0xffffffffu, tm1, 1));
        tm1 = fmaxf(tm1, __shfl_xor_sync(0xffffffffu, tm1, 2));
        float nm0 = fmaxf(m0, tm0), nm1 = fmaxf(m1, tm1);
        float a0 = __expf(m0 - nm0), a1 = __expf(m1 - nm1);
        float gg0 = (nm0 > -0.9e30f) ? 1.f : 0.f;
        float gg1 = (nm1 > -0.9e30f) ? 1.f : 0.f;
        float s0 = 0.f, s1 = 0.f;
#pragma unroll
        for (int nt = 0; nt < 8; nt++) {
            ds[nt][0] = gg0 * __expf(ds[nt][0] - nm0);
            ds[nt][1] = gg0 * __expf(ds[nt][1] - nm0);
            ds[nt][2] = gg1 * __expf(ds[nt][2] - nm1);
            ds[nt][3] = gg1 * __expf(ds[nt][3] - nm1);
            s0 += ds[nt][0] + ds[nt][1];
            s1 += ds[nt][2] + ds[nt][3];
        }
        s0 += __shfl_xor_sync(0xffffffffu, s0, 1);
        s0 += __shfl_xor_sync(0xffffffffu, s0, 2);
        s1 += __shfl_xor_sync(0xffffffffu, s1, 1);
        s1 += __shfl_xor_sync(0xffffffffu, s1, 2);
        l0 = l0 * a0 + s0; m0 = nm0;
        l1 = l1 * a1 + s1; m1 = nm1;
#pragma unroll
        for (int nt = 0; nt < 16; nt++) {
            d_o[nt][0] *= a0; d_o[nt][1] *= a0;
            d_o[nt][2] *= a1; d_o[nt][3] *= a1;
        }

        uint32_t Ph[4][4], Pl[4][4];
#pragma unroll
        for (int kb = 0; kb < 4; kb++) {
            Ph[kb][0] = split2(ds[2*kb][0],   ds[2*kb][1],   Pl[kb][0]);
            Ph[kb][1] = split2(ds[2*kb][2],   ds[2*kb][3],   Pl[kb][1]);
            Ph[kb][2] = split2(ds[2*kb+1][0], ds[2*kb+1][1], Pl[kb][2]);
            Ph[kb][3] = split2(ds[2*kb+1][2], ds[2*kb+1][3], Pl[kb][3]);
        }

        // ---- O += P V: kb outer (accumulation order per acc unchanged),
        //      ntp processed in pairs, pass-structured ----
#pragma unroll
        for (int kb = 0; kb < 4; kb++) {
#pragma unroll
            for (int pp = 0; pp < 4; pp++) {
                int ntp0 = 2 * pp, ntp1 = 2 * pp + 1;
                int hv0 = ntp0 * 16 + vh_sel;
                int hv1 = ntp1 * 16 + vh_sel;
                uint32_t ad0 = stb + 32768 + ((hv0 >> 6) << 13) +
                               SW128((kb * 16 + vrow_l) * 128 + ((hv0 & 63) << 1));
                uint32_t ad1 = stb + 32768 + ((hv1 >> 6) << 13) +
                               SW128((kb * 16 + vrow_l) * 128 + ((hv1 & 63) << 1));
                uint32_t tH0[4], tL0[4], tH1[4], tL1[4];
                LDSM_X4_T(tH0, ad0);
                LDSM_X4_T(tL0, ad0 + 16384);
                LDSM_X4_T(tH1, ad1);
                LDSM_X4_T(tL1, ad1 + 16384);
                // pass 1: Ph x hi
                MMA16816(d_o[2*ntp0],   Ph[kb], tH0[0], tH0[1]);
                MMA16816(d_o[2*ntp0+1], Ph[kb], tH0[2], tH0[3]);
                MMA16816(d_o[2*ntp1],   Ph[kb], tH1[0], tH1[1]);
                MMA16816(d_o[2*ntp1+1], Ph[kb], tH1[2], tH1[3]);
                // pass 2: Pl x hi
                MMA16816(d_o[2*ntp0],   Pl[kb], tH0[0], tH0[1]);
                MMA16816(d_o[2*ntp0+1], Pl[kb], tH0[2], tH0[3]);
                MMA16816(d_o[2*ntp1],   Pl[kb], tH1[0], tH1[1]);
                MMA16816(d_o[2*ntp1+1], Pl[kb], tH1[2], tH1[3]);
                // pass 3: Ph x lo
                MMA16816(d_o[2*ntp0],   Ph[kb], tL0[0], tL0[1]);
                MMA16816(d_o[2*ntp0+1], Ph[kb], tL0[2], tL0[3]);
                MMA16816(d_o[2*ntp1],   Ph[kb], tL1[0], tL1[1]);
                MMA16816(d_o[2*ntp1+1], Ph[kb], tL1[2], tL1[3]);
            }
        }
        __syncthreads();
    }
#undef AT_ISSUE

    float il0 = (l0 > 0.f) ? (1.f / l0) : 0.f;
    float il1 = (l1 > 0.f) ? (1.f / l1) : 0.f;
    size_t base0 = ((size_t)(b * Tt + qbase + r_lo))     * 2048 + n * 128;
    size_t base1 = ((size_t)(b * Tt + qbase + r_lo + 8)) * 2048 + n * 128;
#pragma unroll
    for (int nt = 0; nt < 16; nt++) {
        int h = nt * 8 + (lane & 3) * 2;
        uint32_t lop;
        uint32_t hip = split2(d_o[nt][0] * il0, d_o[nt][1] * il0, lop);
        *(uint32_t*)(g_atthi + base0 + h) = hip;
        *(uint32_t*)(g_attlo + base0 + h) = lop;
        hip = split2(d_o[nt][2] * il1, d_o[nt][3] * il1, lop);
        *(uint32_t*)(g_atthi + base1 + h) = hip;
        *(uint32_t*)(g_attlo + base1 + h) = lop;
    }
}

// ---------------------------------------------------------------------------
extern "C" void kernel_launch(void* const* d_in, const int* in_sizes, int n_in,
                              void* d_out, int out_size) {
    const float* x       = (const float*)d_in[0];
    const int*   seg     = (const int*)  d_in[1];
    const float* wq      = (const float*)d_in[2];
    const float* wk      = (const float*)d_in[3];
    const float* wv      = (const float*)d_in[4];
    const float* wo      = (const float*)d_in[5];
    const float* q_scale = (const float*)d_in[6];
    const float* k_scale = (const float*)d_in[7];
    float* out = (float*)d_out;

    float* qkv;
    cudaGetSymbolAddress((void**)&qkv, g_qkv);
    __nv_bfloat16 *xhi, *xlo, *ahi, *alo;
    __nv_bfloat16 *wch, *wcl, *woh, *wol;
    __nv_bfloat16 *qhh, *qhl, *khh, *khl, *vhh, *vhl;
    cudaGetSymbolAddress((void**)&xhi, g_xhi);
    cudaGetSymbolAddress((void**)&xlo, g_xlo);
    cudaGetSymbolAddress((void**)&ahi, g_atthi);
    cudaGetSymbolAddress((void**)&alo, g_attlo);
    cudaGetSymbolAddress((void**)&wch, g_wqkvT_hi);
    cudaGetSymbolAddress((void**)&wcl, g_wqkvT_lo);
    cudaGetSymbolAddress((void**)&woh, g_woT_hi);
    cudaGetSymbolAddress((void**)&wol, g_woT_lo);
    cudaGetSymbolAddress((void**)&qhh, g_qhh);
    cudaGetSymbolAddress((void**)&qhl, g_qhl);
    cudaGetSymbolAddress((void**)&khh, g_khh);
    cudaGetSymbolAddress((void**)&khl, g_khl);
    cudaGetSymbolAddress((void**)&vhh, g_vhh);
    cudaGetSymbolAddress((void**)&vhl, g_vhl);

    cudaFuncSetAttribute(gemm_hmma, cudaFuncAttributeMaxDynamicSharedMemorySize,
                         GEMM_SMEM);
    cudaFuncSetAttribute(attn_hmma, cudaFuncAttributeMaxDynamicSharedMemorySize,
                         ATT_SMEM);

    pos_kernel<<<Bb, 256>>>(seg);
    rope_kernel<<<Mrows * 64 / 256, 256>>>();

    conv_all<<<7168, 256>>>(x, wq, wk, wv, wo);

    // Combined QKV projection: q|k fp32 -> g_qkv, v -> split head-major
    gemm_hmma<<<dim3(32, Mrows / 256), 256, GEMM_SMEM>>>(
        xhi, xlo, wch, wcl, qkv, vhh, vhl, 3, 4096, 1024);

    // RMSNorm + RoPE(table) + split
    norm_rope_split<<<Mrows * (Nn + Kk) / 2, 256>>>(
        qkv, q_scale, k_scale, qhh, qhl, khh, khl);

    // HMMA flash attention
    attn_hmma<<<dim3(Tt / 64, Kk, Bb), 256, ATT_SMEM>>>(seg);

    // output projection
    gemm_hmma<<<dim3(1024 / 128, Mrows / 256), 256, GEMM_SMEM>>>(
        ahi, alo, woh, wol, out, (__nv_bfloat16*)0, (__nv_bfloat16*)0, 0, 1024, 2048);
}